// round 12
// baseline (speedup 1.0000x reference)
#include <cuda_runtime.h>
#include <cuda_fp16.h>
#include <cstdint>

#define B_ 256
#define I_ 1152
#define N_ 10
#define D_ 16
#define K_ 8

// u_hat scratch, layout [b][n][i][d], fp16 = 94 MB (L2-resident)
__device__ __half g_uhat[(size_t)B_ * N_ * I_ * D_];

// ---------------- helpers ----------------
__device__ __forceinline__ unsigned long long pack2(float a, float b) {
    unsigned long long r;
    asm("mov.b64 %0, {%1, %2};" : "=l"(r) : "f"(a), "f"(b));
    return r;
}
__device__ __forceinline__ unsigned long long fma2(unsigned long long a,
                                                   unsigned long long b,
                                                   unsigned long long c) {
    unsigned long long r;
    asm("fma.rn.f32x2 %0, %1, %2, %3;" : "=l"(r) : "l"(a), "l"(b), "l"(c));
    return r;
}
__device__ __forceinline__ unsigned int cvt2h(unsigned long long v) {
    float lo, hi;
    asm("mov.b64 {%0, %1}, %2;" : "=f"(lo), "=f"(hi) : "l"(v));
    __half2 h = __floats2half2_rn(lo, hi);
    return *reinterpret_cast<unsigned int*>(&h);
}

// ---------------- kernel 1: u_hat = einsum('nidk,bik->bnid') fp16 -------------
// Grid 288 (4-i group, all 256 b). 320 threads = (bq 4) x (iloc 4, n 10, dh 2).
// x staged ONCE for all 256 b as (x,x) u64 (64 KB); hot loop reads pairs of
// duplicated values with LDS.128 (ulonglong2) -> half the LDS instructions.
__global__ __launch_bounds__(320, 2) void k_uhat(const float* __restrict__ x,
                                                 const float* __restrict__ W) {
    __shared__ unsigned long long sx[256 * 32];  // 64 KB: [bl][iloc*8+k]
    const int tid = threadIdx.x;
    const int i0 = blockIdx.x * 4;

    const int bq   = tid / 80;
    const int t    = tid - bq * 80;
    const int dh   = t & 1;
    const int n    = (t >> 1) % 10;
    const int iloc = t / 20;                     // 0..3

    // W regs: w2[k][p] = (W[d0+2p,k], W[d0+2p+1,k]), d0 = dh*8
    unsigned long long w2[8][4];
    {
        float wv[8][8];
        const float* wp = W + (((size_t)n * I_ + i0 + iloc) * D_ + dh * 8) * K_;
#pragma unroll
        for (int d = 0; d < 8; d++) {
            float4 a = *(const float4*)(wp + d * 8);
            float4 c = *(const float4*)(wp + d * 8 + 4);
            wv[d][0] = a.x; wv[d][1] = a.y; wv[d][2] = a.z; wv[d][3] = a.w;
            wv[d][4] = c.x; wv[d][5] = c.y; wv[d][6] = c.z; wv[d][7] = c.w;
        }
#pragma unroll
        for (int k = 0; k < 8; k++)
#pragma unroll
            for (int p = 0; p < 4; p++)
                w2[k][p] = pack2(wv[2 * p][k], wv[2 * p + 1][k]);
    }

    for (int idx = tid; idx < 8192; idx += 320) {
        int bl = idx >> 5, rem = idx & 31;
        float v = x[(size_t)bl * (I_ * K_) + i0 * K_ + rem];
        sx[idx] = pack2(v, v);
    }
    __syncthreads();

    const int b0 = bq * 64;
#pragma unroll 2
    for (int j = 0; j < 64; j++) {
        const int bl = b0 + j;
        const ulonglong2* xr = (const ulonglong2*)(sx + bl * 32 + iloc * 8);
        unsigned long long a0 = 0ull, a1 = 0ull, a2 = 0ull, a3 = 0ull;
#pragma unroll
        for (int kp = 0; kp < 4; kp++) {
            ulonglong2 xx = xr[kp];
            a0 = fma2(w2[2 * kp][0], xx.x, a0);
            a1 = fma2(w2[2 * kp][1], xx.x, a1);
            a2 = fma2(w2[2 * kp][2], xx.x, a2);
            a3 = fma2(w2[2 * kp][3], xx.x, a3);
            a0 = fma2(w2[2 * kp + 1][0], xx.y, a0);
            a1 = fma2(w2[2 * kp + 1][1], xx.y, a1);
            a2 = fma2(w2[2 * kp + 1][2], xx.y, a2);
            a3 = fma2(w2[2 * kp + 1][3], xx.y, a3);
        }
        uint4 r;
        r.x = cvt2h(a0); r.y = cvt2h(a1); r.z = cvt2h(a2); r.w = cvt2h(a3);
        *(uint4*)(g_uhat + (((size_t)bl * N_ + n) * I_ + i0 + iloc) * D_ + dh * 8) = r;
    }
}

// ---------------- kernel 2: routing, 576 threads/CTA, i-tiled A/B (L1 reuse) --
#define RTH 576
#define TILE_I 288
#define CSTRIDE 292

__global__ __launch_bounds__(RTH, 2) void k_route(float* __restrict__ out) {
    __shared__ __align__(16) float cbuf[10 * CSTRIDE];   // c for current tile
    __shared__ __align__(16) float sPart[18 * 80];
    __shared__ __align__(16) float stot[160];
    __shared__ __align__(16) float ocum[160];
    __shared__ __align__(16) unsigned int ocum_h[80];    // ocum as half2

    const int tid = threadIdx.x;
    const int b = blockIdx.x;
    const __half* ub = g_uhat + (size_t)b * N_ * I_ * D_;

    const int w = tid >> 5, lane = tid & 31;
    const int il = lane >> 2, dq = lane & 3;
    const int nh = w & 1, wg = w >> 1;          // wg 0..8
    const int nbase = nh * 5;
    const int ia = tid >> 1, dhh = tid & 1;     // sweep-A mapping

#pragma unroll 1
    for (int r = 0; r < 3; r++) {
        float sp[5][4];
#pragma unroll
        for (int n = 0; n < 5; n++)
#pragma unroll
            for (int q = 0; q < 4; q++) sp[n][q] = 0.0f;

#pragma unroll 1
        for (int tile = 0; tile < 4; tile++) {
            const int i0t = tile * TILE_I;

            // ---- sweep A on tile: (i, d-half) threads, fp16 dots ----
            if (r > 0) {
                const int i = i0t + ia;
                float lg[10];
#pragma unroll 2
                for (int n = 0; n < 10; n++) {
                    uint4 v = *(const uint4*)(ub + ((size_t)n * I_ + i) * D_ + dhh * 8);
                    uint4 o = ((const uint4*)ocum_h)[n * 2 + dhh];
                    __half2 acc = __float2half2_rn(0.0f);
                    acc = __hfma2(*(const __half2*)&v.x, *(const __half2*)&o.x, acc);
                    acc = __hfma2(*(const __half2*)&v.y, *(const __half2*)&o.y, acc);
                    acc = __hfma2(*(const __half2*)&v.z, *(const __half2*)&o.z, acc);
                    acc = __hfma2(*(const __half2*)&v.w, *(const __half2*)&o.w, acc);
                    float2 fa = __half22float2(acc);
                    lg[n] = fa.x + fa.y;
                }
                // combine d-halves across the lane pair
#pragma unroll
                for (int n = 0; n < 10; n++)
                    lg[n] += __shfl_xor_sync(0xffffffffu, lg[n], 1);
                float m = lg[0];
#pragma unroll
                for (int n = 1; n < 10; n++) m = fmaxf(m, lg[n]);
                float sum = 0.0f;
#pragma unroll
                for (int n = 0; n < 10; n++) { lg[n] = __expf(lg[n] - m); sum += lg[n]; }
                float inv = __fdividef(1.0f, sum);
#pragma unroll
                for (int n = 0; n < 10; n++) cbuf[n * CSTRIDE + ia] = lg[n] * inv;
                __syncthreads();
            }

            // ---- sweep B on tile: 4 rounds x 5 n, reads hit L1 ----
#pragma unroll 2
            for (int round = 0; round < 4; round++) {
                const int ic = round * 72 + wg * 8 + il;      // i within tile
                const __half* ubase = ub + ((size_t)nbase * I_ + i0t + ic) * D_ + dq * 4;
#pragma unroll
                for (int n = 0; n < 5; n++) {
                    uint2 v = *(const uint2*)(ubase + (size_t)n * (I_ * D_));
                    float2 f0 = __half22float2(*(const __half2*)&v.x);
                    float2 f1 = __half22float2(*(const __half2*)&v.y);
                    float cv = (r == 0) ? 0.1f : cbuf[(nbase + n) * CSTRIDE + ic];
                    sp[n][0] += cv * f0.x;
                    sp[n][1] += cv * f0.y;
                    sp[n][2] += cv * f1.x;
                    sp[n][3] += cv * f1.y;
                }
            }
            if (r > 0) __syncthreads();   // cbuf consumed before next tile
        }

        // ---- reduce sp over il lanes within warp ----
#pragma unroll
        for (int ofs = 4; ofs <= 16; ofs <<= 1)
#pragma unroll
            for (int n = 0; n < 5; n++)
#pragma unroll
                for (int q = 0; q < 4; q++)
                    sp[n][q] += __shfl_xor_sync(0xffffffffu, sp[n][q], ofs);

        if (il == 0) {
#pragma unroll
            for (int n = 0; n < 5; n++)
                *(float4*)&sPart[w * 80 + n * 16 + dq * 4] =
                    make_float4(sp[n][0], sp[n][1], sp[n][2], sp[n][3]);
        }
        __syncthreads();

        if (tid < 160) {
            const int n = tid >> 4;
            const int nh2 = (n >= 5);
            const int col = (n - nh2 * 5) * 16 + (tid & 15);
            float s = 0.0f;
#pragma unroll
            for (int j = 0; j < 9; j++) s += sPart[(j * 2 + nh2) * 80 + col];
            stot[tid] = s;
        }
        __syncthreads();

        if (tid < 160) {
            const int n = tid >> 4;
            float ns = 0.0f;
#pragma unroll
            for (int j = 0; j < 16; j++) {
                float tv = stot[n * 16 + j];
                ns += tv * tv;
            }
            float f = sqrtf(ns) / (1.0f + ns);
            float val = stot[tid] * f;
            if (r < 2) ocum[tid] = (r == 0) ? val : ocum[tid] + val;
            else       out[b * 160 + tid] = val;
        }
        __syncthreads();

        if (r < 2) {
            if (tid < 80) {
                __half2 h = __floats2half2_rn(ocum[tid * 2], ocum[tid * 2 + 1]);
                ocum_h[tid] = *reinterpret_cast<unsigned int*>(&h);
            }
            __syncthreads();
        }
    }
}

// ---------------- launch ----------------
extern "C" void kernel_launch(void* const* d_in, const int* in_sizes, int n_in,
                              void* d_out, int out_size) {
    const float* x = (const float*)d_in[0];   // inputs [B, I, Din]
    const float* W = (const float*)d_in[1];   // W      [N, I, D, Din]
    if (n_in >= 2 && in_sizes[0] == N_ * I_ * D_ * K_) {
        const float* t = x; x = W; W = t;
    }
    float* out = (float*)d_out;

    k_uhat<<<I_ / 4, 320>>>(x, W);
    k_route<<<B_, RTH>>>(out);
}

// round 13
// speedup vs baseline: 1.0207x; 1.0207x over previous
#include <cuda_runtime.h>
#include <cuda_fp16.h>
#include <cstdint>

#define B_ 256
#define I_ 1152
#define N_ 10
#define D_ 16
#define K_ 8

// u_hat scratch, layout [b][n][i][d], fp16 = 94 MB (L2-resident)
__device__ __half g_uhat[(size_t)B_ * N_ * I_ * D_];

// ---------------- helpers ----------------
__device__ __forceinline__ unsigned long long pack2(float a, float b) {
    unsigned long long r;
    asm("mov.b64 %0, {%1, %2};" : "=l"(r) : "f"(a), "f"(b));
    return r;
}
__device__ __forceinline__ unsigned long long fma2(unsigned long long a,
                                                   unsigned long long b,
                                                   unsigned long long c) {
    unsigned long long r;
    asm("fma.rn.f32x2 %0, %1, %2, %3;" : "=l"(r) : "l"(a), "l"(b), "l"(c));
    return r;
}
__device__ __forceinline__ void unpack2(unsigned long long v, float& lo, float& hi) {
    asm("mov.b64 {%0, %1}, %2;" : "=f"(lo), "=f"(hi) : "l"(v));
}
__device__ __forceinline__ unsigned int cvt2h(unsigned long long v) {
    float lo, hi;
    unpack2(v, lo, hi);
    __half2 h = __floats2half2_rn(lo, hi);
    return *reinterpret_cast<unsigned int*>(&h);
}

// ---------------- kernel 1: u_hat = einsum('nidk,bik->bnid') fp16 -------------
__global__ __launch_bounds__(320, 2) void k_uhat(const float* __restrict__ x,
                                                 const float* __restrict__ W) {
    __shared__ unsigned long long sx[256 * 32];  // 64 KB: [bl][iloc*8+k]
    const int tid = threadIdx.x;
    const int i0 = blockIdx.x * 4;

    const int bq   = tid / 80;
    const int t    = tid - bq * 80;
    const int dh   = t & 1;
    const int n    = (t >> 1) % 10;
    const int iloc = t / 20;

    unsigned long long w2[8][4];
    {
        float wv[8][8];
        const float* wp = W + (((size_t)n * I_ + i0 + iloc) * D_ + dh * 8) * K_;
#pragma unroll
        for (int d = 0; d < 8; d++) {
            float4 a = *(const float4*)(wp + d * 8);
            float4 c = *(const float4*)(wp + d * 8 + 4);
            wv[d][0] = a.x; wv[d][1] = a.y; wv[d][2] = a.z; wv[d][3] = a.w;
            wv[d][4] = c.x; wv[d][5] = c.y; wv[d][6] = c.z; wv[d][7] = c.w;
        }
#pragma unroll
        for (int k = 0; k < 8; k++)
#pragma unroll
            for (int p = 0; p < 4; p++)
                w2[k][p] = pack2(wv[2 * p][k], wv[2 * p + 1][k]);
    }

    for (int idx = tid; idx < 8192; idx += 320) {
        int bl = idx >> 5, rem = idx & 31;
        float v = x[(size_t)bl * (I_ * K_) + i0 * K_ + rem];
        sx[idx] = pack2(v, v);
    }
    __syncthreads();

    const int b0 = bq * 64;
#pragma unroll 2
    for (int j = 0; j < 64; j++) {
        const int bl = b0 + j;
        const ulonglong2* xr = (const ulonglong2*)(sx + bl * 32 + iloc * 8);
        unsigned long long a0 = 0ull, a1 = 0ull, a2 = 0ull, a3 = 0ull;
#pragma unroll
        for (int kp = 0; kp < 4; kp++) {
            ulonglong2 xx = xr[kp];
            a0 = fma2(w2[2 * kp][0], xx.x, a0);
            a1 = fma2(w2[2 * kp][1], xx.x, a1);
            a2 = fma2(w2[2 * kp][2], xx.x, a2);
            a3 = fma2(w2[2 * kp][3], xx.x, a3);
            a0 = fma2(w2[2 * kp + 1][0], xx.y, a0);
            a1 = fma2(w2[2 * kp + 1][1], xx.y, a1);
            a2 = fma2(w2[2 * kp + 1][2], xx.y, a2);
            a3 = fma2(w2[2 * kp + 1][3], xx.y, a3);
        }
        uint4 r;
        r.x = cvt2h(a0); r.y = cvt2h(a1); r.z = cvt2h(a2); r.w = cvt2h(a3);
        *(uint4*)(g_uhat + (((size_t)bl * N_ + n) * I_ + i0 + iloc) * D_ + dh * 8) = r;
    }
}

// ---------------- kernel 2: routing, 576 threads per b, untiled ---------------
#define RTH 576
#define CSTRIDE 1160

__device__ __forceinline__ void sweepB(const __half* __restrict__ ub,
                                       const float* __restrict__ cbuf,
                                       unsigned long long sp[5][2],
                                       int nbase, int wg, int il, int dq,
                                       bool constC) {
#pragma unroll 2
    for (int round = 0; round < 16; round++) {
        const int i = round * 72 + wg * 8 + il;
        const __half* ubase = ub + ((size_t)nbase * I_ + i) * D_ + dq * 4;
#pragma unroll
        for (int n = 0; n < 5; n++) {
            uint2 v = *(const uint2*)(ubase + (size_t)n * (I_ * D_));
            float2 f0 = __half22float2(*(const __half2*)&v.x);
            float2 f1 = __half22float2(*(const __half2*)&v.y);
            float cv = constC ? 0.1f : cbuf[(nbase + n) * CSTRIDE + i];
            unsigned long long cc = pack2(cv, cv);
            sp[n][0] = fma2(pack2(f0.x, f0.y), cc, sp[n][0]);
            sp[n][1] = fma2(pack2(f1.x, f1.y), cc, sp[n][1]);
        }
    }
}

__global__ __launch_bounds__(RTH, 2) void k_route(float* __restrict__ out) {
    __shared__ __align__(16) float cbuf[10 * CSTRIDE];   // 46.4 KB, whole I
    __shared__ __align__(16) float sPart[18 * 80];
    __shared__ __align__(16) float stot[160];
    __shared__ __align__(16) float ocum[160];
    __shared__ __align__(16) unsigned int ocum_h[80];    // ocum*log2e as half2

    const int tid = threadIdx.x;
    const int b = blockIdx.x;
    const __half* ub = g_uhat + (size_t)b * N_ * I_ * D_;

    const int w = tid >> 5, lane = tid & 31;
    const int il = lane >> 2, dq = lane & 3;
    const int nh = w & 1, wg = w >> 1;
    const int nbase = nh * 5;

#pragma unroll 1
    for (int r = 0; r < 3; r++) {
        // ---- sweep A over ALL I (full-d per thread, no shuffles) ----
        if (r > 0) {
#pragma unroll 1
            for (int i = tid; i < I_; i += RTH) {
                float lg[10];
#pragma unroll 2
                for (int n = 0; n < 10; n++) {
                    const uint4* p = (const uint4*)(ub + ((size_t)n * I_ + i) * D_);
                    uint4 v0 = p[0], v1 = p[1];
                    uint4 o0 = ((const uint4*)ocum_h)[n * 2];
                    uint4 o1 = ((const uint4*)ocum_h)[n * 2 + 1];
                    __half2 acc = __float2half2_rn(0.0f);
                    acc = __hfma2(*(const __half2*)&v0.x, *(const __half2*)&o0.x, acc);
                    acc = __hfma2(*(const __half2*)&v0.y, *(const __half2*)&o0.y, acc);
                    acc = __hfma2(*(const __half2*)&v0.z, *(const __half2*)&o0.z, acc);
                    acc = __hfma2(*(const __half2*)&v0.w, *(const __half2*)&o0.w, acc);
                    acc = __hfma2(*(const __half2*)&v1.x, *(const __half2*)&o1.x, acc);
                    acc = __hfma2(*(const __half2*)&v1.y, *(const __half2*)&o1.y, acc);
                    acc = __hfma2(*(const __half2*)&v1.z, *(const __half2*)&o1.z, acc);
                    acc = __hfma2(*(const __half2*)&v1.w, *(const __half2*)&o1.w, acc);
                    float2 fa = __half22float2(acc);
                    lg[n] = fa.x + fa.y;           // already scaled by log2e
                }
                // softmax without max-subtraction (|logit| small, exp2 safe)
                float sum = 0.0f;
#pragma unroll
                for (int n = 0; n < 10; n++) { lg[n] = exp2f(lg[n]); sum += lg[n]; }
                float inv = __fdividef(1.0f, sum);
#pragma unroll
                for (int n = 0; n < 10; n++) cbuf[n * CSTRIDE + i] = lg[n] * inv;
            }
            __syncthreads();
        }

        // ---- sweep B (sp declared here so A can reuse the registers) ----
        unsigned long long sp[5][2];
#pragma unroll
        for (int n = 0; n < 5; n++) { sp[n][0] = 0ull; sp[n][1] = 0ull; }

        if (r == 0) sweepB(ub, cbuf, sp, nbase, wg, il, dq, true);
        else        sweepB(ub, cbuf, sp, nbase, wg, il, dq, false);

        // unpack and reduce over il lanes
        float s4[5][4];
#pragma unroll
        for (int n = 0; n < 5; n++) {
            unpack2(sp[n][0], s4[n][0], s4[n][1]);
            unpack2(sp[n][1], s4[n][2], s4[n][3]);
        }
#pragma unroll
        for (int ofs = 4; ofs <= 16; ofs <<= 1)
#pragma unroll
            for (int n = 0; n < 5; n++)
#pragma unroll
                for (int q = 0; q < 4; q++)
                    s4[n][q] += __shfl_xor_sync(0xffffffffu, s4[n][q], ofs);

        if (il == 0) {
#pragma unroll
            for (int n = 0; n < 5; n++)
                *(float4*)&sPart[w * 80 + n * 16 + dq * 4] =
                    make_float4(s4[n][0], s4[n][1], s4[n][2], s4[n][3]);
        }
        __syncthreads();

        if (tid < 160) {
            const int n = tid >> 4;
            const int nh2 = (n >= 5);
            const int col = (n - nh2 * 5) * 16 + (tid & 15);
            float s = 0.0f;
#pragma unroll
            for (int j = 0; j < 9; j++) s += sPart[(j * 2 + nh2) * 80 + col];
            stot[tid] = s;
        }
        __syncthreads();

        if (tid < 160) {
            const int n = tid >> 4;
            float ns = 0.0f;
#pragma unroll
            for (int j = 0; j < 16; j++) {
                float tv = stot[n * 16 + j];
                ns += tv * tv;
            }
            float f = sqrtf(ns) / (1.0f + ns);
            float val = stot[tid] * f;
            if (r < 2) ocum[tid] = (r == 0) ? val : ocum[tid] + val;
            else       out[b * 160 + tid] = val;
        }
        __syncthreads();

        if (r < 2) {
            if (tid < 80) {
                const float L2E = 1.44269504f;
                __half2 h = __floats2half2_rn(ocum[tid * 2] * L2E,
                                              ocum[tid * 2 + 1] * L2E);
                ocum_h[tid] = *reinterpret_cast<unsigned int*>(&h);
            }
            __syncthreads();
        }
    }
}

// ---------------- launch ----------------
extern "C" void kernel_launch(void* const* d_in, const int* in_sizes, int n_in,
                              void* d_out, int out_size) {
    const float* x = (const float*)d_in[0];   // inputs [B, I, Din]
    const float* W = (const float*)d_in[1];   // W      [N, I, D, Din]
    if (n_in >= 2 && in_sizes[0] == N_ * I_ * D_ * K_) {
        const float* t = x; x = W; W = t;
    }
    float* out = (float*)d_out;

    k_uhat<<<I_ / 4, 320>>>(x, W);
    k_route<<<B_, RTH>>>(out);
}